// round 16
// baseline (speedup 1.0000x reference)
#include <cuda_runtime.h>
#include <math.h>

#define BB 32
#define NN 1025
#define DD 768
#define HH 12
#define KK 257   // context length
#define NK (NN*KK)

// ---------------- scratch (device globals; no allocs allowed) ----------------
__device__ float g_ctx [BB * KK * DD];        // [B,257,768]  (tf32-rounded)
__device__ float g_xr  [BB * NN * DD];        // tf32-rounded copy of x
__device__ float g_q   [BB * NN * DD];        // [B,1025,768]
__device__ float g_kv  [BB * KK * 2 * DD];    // [B,257,1536]  (k | v)
__device__ float g_bias[HH * NN * KK];        // [12,1025,257]
__device__ float g_o   [BB * NN * DD];        // [B,1025,768]  (tf32-rounded)
__device__ float g_wqr [DD * DD];             // tf32-rounded Wq
__device__ float g_wkvr[2 * DD * DD];         // tf32-rounded Wkv
__device__ float g_wor [DD * DD];             // tf32-rounded Wo

// ---------------- helpers ----------------
__device__ __forceinline__ unsigned f2tf(float f) {
    unsigned u; asm("cvt.rna.tf32.f32 %0, %1;" : "=r"(u) : "f"(f)); return u;
}
__device__ __forceinline__ float rtf(float f) {      // round fp32 -> tf32-in-fp32
    return __uint_as_float(f2tf(f));
}
__device__ __forceinline__ float4 rtf4(float4 v) {
    return make_float4(rtf(v.x), rtf(v.y), rtf(v.z), rtf(v.w));
}

#define MMA_TF32(cc, aa, bb)                                                   \
    asm volatile("mma.sync.aligned.m16n8k8.row.col.f32.tf32.tf32.f32 "         \
                 "{%0,%1,%2,%3}, {%4,%5,%6,%7}, {%8,%9}, {%0,%1,%2,%3};"       \
                 : "+f"(cc[0]), "+f"(cc[1]), "+f"(cc[2]), "+f"(cc[3])          \
                 : "r"(aa[0]), "r"(aa[1]), "r"(aa[2]), "r"(aa[3]),             \
                   "r"(bb[0]), "r"(bb[1]));

__device__ __forceinline__ void cp16(float* smem_dst, const float* gsrc, bool pred) {
    unsigned sa = (unsigned)__cvta_generic_to_shared(smem_dst);
    int sz = pred ? 16 : 0;
    asm volatile("cp.async.cg.shared.global [%0], [%1], 16, %2;"
                 :: "r"(sa), "l"(gsrc), "r"(sz));
}
#define CP_COMMIT() asm volatile("cp.async.commit_group;")
#define CP_WAIT2()  asm volatile("cp.async.wait_group 2;")

// ---------------- 0) tf32 rounding for weights ----------------
__global__ __launch_bounds__(256)
void round_kernel(const float* __restrict__ src, float* __restrict__ dst, int n4)
{
    int i = blockIdx.x * blockDim.x + threadIdx.x;
    if (i < n4) ((float4*)dst)[i] = rtf4(((const float4*)src)[i]);
}

// ---------------- 1) tiled local pooling -> ctx (+ rounded x copy) ---------
__global__ __launch_bounds__(256)
void pool_kernel(const float* __restrict__ x, const float* __restrict__ Wl,
                 float* __restrict__ ctx, float* __restrict__ xr)
{
    __shared__ float xs[4][768];
    __shared__ float red[4][8];
    __shared__ float ws[4];
    int t = blockIdx.x, b = blockIdx.y;
    int tid = threadIdx.x;
    const float* xb = x + (size_t)b * NN * DD;
    float* xrb = xr + (size_t)b * NN * DD;
    float* cout = ctx + ((size_t)b * KK + t) * DD;

    if (t == 0) {
        for (int i = tid; i < 192; i += 256) {
            float4 v = ((const float4*)xb)[i];
            float4 rv = rtf4(v);
            ((float4*)cout)[i] = rv;       // register token -> ctx (rounded)
            ((float4*)xrb)[i]  = rv;       // row 0 of rounded x
        }
        return;
    }
    int tt = t - 1, ti = tt >> 4, tj = tt & 15;
    int rows[4];
#pragma unroll
    for (int i = 0; i < 4; i++)
        rows[i] = 1 + (ti * 2 + (i >> 1)) * 32 + tj * 2 + (i & 1);

    for (int i = tid; i < 4 * 192; i += 256) {
        int rr = i / 192, seg = i - rr * 192;
        float4 v = ((const float4*)(xb + (size_t)rows[rr] * DD))[seg];
        ((float4*)&xs[rr][0])[seg] = v;
        ((float4*)(xrb + (size_t)rows[rr] * DD))[seg] = rtf4(v);
    }
    __syncthreads();

    float p0 = 0.f, p1 = 0.f, p2 = 0.f, p3 = 0.f;
    for (int dm = tid; dm < DD; dm += 256) {
        float wv = Wl[dm];
        p0 = fmaf(xs[0][dm], wv, p0);
        p1 = fmaf(xs[1][dm], wv, p1);
        p2 = fmaf(xs[2][dm], wv, p2);
        p3 = fmaf(xs[3][dm], wv, p3);
    }
#pragma unroll
    for (int off = 16; off; off >>= 1) {
        p0 += __shfl_xor_sync(0xffffffffu, p0, off);
        p1 += __shfl_xor_sync(0xffffffffu, p1, off);
        p2 += __shfl_xor_sync(0xffffffffu, p2, off);
        p3 += __shfl_xor_sync(0xffffffffu, p3, off);
    }
    if ((tid & 31) == 0) {
        int wgi = tid >> 5;
        red[0][wgi] = p0; red[1][wgi] = p1; red[2][wgi] = p2; red[3][wgi] = p3;
    }
    __syncthreads();
    if (tid == 0) {
        float s[4];
#pragma unroll
        for (int i = 0; i < 4; i++) {
            float a = 0.f;
#pragma unroll
            for (int wgi = 0; wgi < 8; wgi++) a += red[i][wgi];
            s[i] = a;
        }
        float mx = fmaxf(fmaxf(s[0], s[1]), fmaxf(s[2], s[3]));
        float e0 = __expf(s[0] - mx), e1 = __expf(s[1] - mx);
        float e2 = __expf(s[2] - mx), e3 = __expf(s[3] - mx);
        float inv = 1.f / (e0 + e1 + e2 + e3);
        ws[0] = e0 * inv; ws[1] = e1 * inv; ws[2] = e2 * inv; ws[3] = e3 * inv;
    }
    __syncthreads();
    for (int dm = tid; dm < DD; dm += 256) {
        cout[dm] = rtf(ws[0] * xs[0][dm] + ws[1] * xs[1][dm]
                     + ws[2] * xs[2][dm] + ws[3] * xs[3][dm]);
    }
}

// ---------------- 2) tf32 NT GEMM: 128x256 tile, 4-stage cp.async, occ=1 ---
// Operands PRE-ROUNDED to tf32; raw bits feed mma directly.
// A region: 4 stages * 128*20 = 10240 floats; B region: 4 * 256*20 = 20480.
#define AS(s,r,k) gsm[(((s) * 128 + (r)) * 20) + (k)]
#define BS(s,r,k) gsm[10240 + (((s) * 256 + (r)) * 20) + (k)]

__global__ __launch_bounds__(256, 1)
void gemm_tf32(const float* __restrict__ A, const float* __restrict__ B,
               float* __restrict__ C, int M, int N, int K,
               const float* __restrict__ bias)
{
    extern __shared__ __align__(16) float gsm[];   // 30720 floats = 120 KB

    const int tid  = threadIdx.x;
    const int lane = tid & 31, w = tid >> 5;
    const int g = lane >> 2, t4 = lane & 3;
    const int wm = (w >> 2) * 64;            // 0 or 64
    const int wn = (w & 3) * 64;             // 0,64,128,192
    const int bm = blockIdx.y * 128, bn = blockIdx.x * 256;

    const int lrow = tid >> 2;               // 0..63
    const int lk   = (tid & 3) << 2;         // 0,4,8,12

    // A row clamps (rows can exceed M on the last block-row)
    const int ar0 = bm + lrow,      ar1 = bm + lrow + 64;
    const bool av0 = ar0 < M,       av1 = ar1 < M;
    const int ac0 = av0 ? ar0 : 0,  ac1 = av1 ? ar1 : 0;
    // B rows: N is a multiple of 256 -> always valid
    const int br0 = bn + lrow, br1 = br0 + 64, br2 = br0 + 128, br3 = br0 + 192;

    float c[4][8][4];
#pragma unroll
    for (int i = 0; i < 4; i++)
#pragma unroll
        for (int j = 0; j < 8; j++)
#pragma unroll
            for (int e = 0; e < 4; e++) c[i][j][e] = 0.f;

    const int nkt = K / 16;

    // ---- prologue: fill stages 0..2 ----
#pragma unroll
    for (int s = 0; s < 3; s++) {
        const int k0 = s * 16;
        cp16(&AS(s, lrow,       lk), A + (size_t)ac0 * K + k0 + lk, av0);
        cp16(&AS(s, lrow + 64,  lk), A + (size_t)ac1 * K + k0 + lk, av1);
        cp16(&BS(s, lrow,       lk), B + (size_t)br0 * K + k0 + lk, true);
        cp16(&BS(s, lrow + 64,  lk), B + (size_t)br1 * K + k0 + lk, true);
        cp16(&BS(s, lrow + 128, lk), B + (size_t)br2 * K + k0 + lk, true);
        cp16(&BS(s, lrow + 192, lk), B + (size_t)br3 * K + k0 + lk, true);
        CP_COMMIT();
    }

    for (int kt = 0; kt < nkt; kt++) {
        CP_WAIT2();              // group kt complete (<=2 newer pending)
        __syncthreads();
        const int st = kt & 3;

#pragma unroll
        for (int ks = 0; ks < 2; ks++) {
            const int kk = ks * 8;
            unsigned af[4][4];
#pragma unroll
            for (int i = 0; i < 4; i++) {
                int r = wm + i * 16 + g;
                af[i][0] = __float_as_uint(AS(st, r,     kk + t4));
                af[i][1] = __float_as_uint(AS(st, r + 8, kk + t4));
                af[i][2] = __float_as_uint(AS(st, r,     kk + t4 + 4));
                af[i][3] = __float_as_uint(AS(st, r + 8, kk + t4 + 4));
            }
#pragma unroll
            for (int j = 0; j < 8; j++) {
                unsigned bf[2];
                int r = wn + j * 8 + g;
                bf[0] = __float_as_uint(BS(st, r, kk + t4));
                bf[1] = __float_as_uint(BS(st, r, kk + t4 + 4));
#pragma unroll
                for (int i = 0; i < 4; i++)
                    MMA_TF32(c[i][j], af[i], bf);
            }
        }

        // prefetch tile kt+3 into stage (kt+3)&3 (safe: barrier above)
        const int pf = kt + 3;
        if (pf < nkt) {
            const int s = pf & 3, k0 = pf * 16;
            cp16(&AS(s, lrow,       lk), A + (size_t)ac0 * K + k0 + lk, av0);
            cp16(&AS(s, lrow + 64,  lk), A + (size_t)ac1 * K + k0 + lk, av1);
            cp16(&BS(s, lrow,       lk), B + (size_t)br0 * K + k0 + lk, true);
            cp16(&BS(s, lrow + 64,  lk), B + (size_t)br1 * K + k0 + lk, true);
            cp16(&BS(s, lrow + 128, lk), B + (size_t)br2 * K + k0 + lk, true);
            cp16(&BS(s, lrow + 192, lk), B + (size_t)br3 * K + k0 + lk, true);
        }
        CP_COMMIT();
    }

    // ---- epilogue ----
#pragma unroll
    for (int j = 0; j < 8; j++) {
        const int col = bn + wn + j * 8 + t4 * 2;
        float b0 = bias ? bias[col] : 0.f;
        float b1 = bias ? bias[col + 1] : 0.f;
#pragma unroll
        for (int i = 0; i < 4; i++) {
            int r0 = bm + wm + i * 16 + g;
            if (r0 < M)
                *(float2*)(C + (size_t)r0 * N + col) =
                    make_float2(c[i][j][0] + b0, c[i][j][1] + b1);
            int r1 = r0 + 8;
            if (r1 < M)
                *(float2*)(C + (size_t)r1 * N + col) =
                    make_float2(c[i][j][2] + b0, c[i][j][3] + b1);
        }
    }
}
#define GEMM_SMEM ((10240 + 20480) * 4)   // 122880 bytes

// ---------------- 3) CPB relative-position bias ----------------
__global__ __launch_bounds__(128)
void cpb_kernel(const float* __restrict__ feats, const float* __restrict__ mask,
                const float* __restrict__ w1, const float* __restrict__ b1,
                const float* __restrict__ w2, const float* __restrict__ b2,
                float* __restrict__ bias)
{
    int idx = blockIdx.x * blockDim.x + threadIdx.x;
    if (idx >= NK) return;
    float f0 = feats[2 * idx], f1 = feats[2 * idx + 1];
    float m = mask[idx];
    float h[32];
#pragma unroll
    for (int c = 0; c < 32; c++) {
        float t = fmaf(f0, w1[2 * c], fmaf(f1, w1[2 * c + 1], b1[c]));
        h[c] = 0.5f * t * (1.f + erff(t * 0.7071067811865475f));
    }
#pragma unroll
    for (int hh = 0; hh < HH; hh++) {
        float s = b2[hh];
#pragma unroll
        for (int c = 0; c < 32; c++) s = fmaf(w2[hh * 32 + c], h[c], s);
        bias[(size_t)hh * NK + idx] = s * m;
    }
}

// ---------------- 4) mma flash attention (writes tf32-rounded o) -----------
#define QT   128
#define KP   264
#define NJT  33     // KP/8
#define QSTR 68
#define KSTR 68
#define VSTR 72

__global__ __launch_bounds__(256, 1)
void attn_mma(const float* __restrict__ q, const float* __restrict__ kv,
              const float* __restrict__ bias, float* __restrict__ o)
{
    extern __shared__ unsigned smu[];
    unsigned* Qs = smu;                       // [128][68]
    unsigned* Ks = Qs + QT * QSTR;            // [264][68]
    unsigned* Vs = Ks + KP * KSTR;            // [264][72]

    const int qb0 = blockIdx.x * QT;
    const int h = blockIdx.y, b = blockIdx.z;
    const int tid = threadIdx.x, w = tid >> 5, lane = tid & 31;
    const int g = lane >> 2, t4 = lane & 3;
    const float4 z4 = make_float4(0.f, 0.f, 0.f, 0.f);

    // ---- stage Q (tf32) ----
    const float* qbase = q + (size_t)b * NN * DD + (size_t)h * 64;
    for (int i = tid; i < QT * 16; i += 256) {
        int r = i >> 4, seg = i & 15;
        int n = qb0 + r;
        float4 v = (n < NN) ? *(const float4*)(qbase + (size_t)n * DD + seg * 4) : z4;
        unsigned* dst = Qs + r * QSTR + seg * 4;
        dst[0] = f2tf(v.x); dst[1] = f2tf(v.y); dst[2] = f2tf(v.z); dst[3] = f2tf(v.w);
    }
    // ---- stage K, V (tf32) ----
    const float* kbase = kv + (size_t)b * KK * (2 * DD) + (size_t)h * 64;
    for (int i = tid; i < KP * 16; i += 256) {
        int r = i >> 4, seg = i & 15;
        float4 kvv = z4, vvv = z4;
        if (r < KK) {
            kvv = *(const float4*)(kbase + (size_t)r * (2 * DD) + seg * 4);
            vvv = *(const float4*)(kbase + (size_t)r * (2 * DD) + DD + seg * 4);
        }
        unsigned* kd = Ks + r * KSTR + seg * 4;
        kd[0] = f2tf(kvv.x); kd[1] = f2tf(kvv.y); kd[2] = f2tf(kvv.z); kd[3] = f2tf(kvv.w);
        unsigned* vd = Vs + r * VSTR + seg * 4;
        vd[0] = f2tf(vvv.x); vd[1] = f2tf(vvv.y); vd[2] = f2tf(vvv.z); vd[3] = f2tf(vvv.w);
    }
    __syncthreads();

    // ---- QK^T : S[16 x 264] per warp ----
    const int wq = w * 16;
    unsigned aq[8][4];
#pragma unroll
    for (int kt = 0; kt < 8; kt++) {
        int kk = kt * 8;
        aq[kt][0] = Qs[(wq + g    ) * QSTR + kk + t4];
        aq[kt][1] = Qs[(wq + g + 8) * QSTR + kk + t4];
        aq[kt][2] = Qs[(wq + g    ) * QSTR + kk + t4 + 4];
        aq[kt][3] = Qs[(wq + g + 8) * QSTR + kk + t4 + 4];
    }

    float s[NJT][4];
#pragma unroll
    for (int j = 0; j < NJT; j++) {
        s[j][0] = s[j][1] = s[j][2] = s[j][3] = 0.f;
#pragma unroll
        for (int kt = 0; kt < 8; kt++) {
            unsigned bf[2];
            const unsigned* kp = Ks + (j * 8 + g) * KSTR + kt * 8 + t4;
            bf[0] = kp[0];
            bf[1] = kp[4];
            MMA_TF32(s[j], aq[kt], bf);
        }
    }

    // ---- scale + bias ----
    const int nrow0 = qb0 + wq + g;
    const int nrow1 = nrow0 + 8;
    const float* bp0 = bias + ((size_t)h * NN + (nrow0 < NN ? nrow0 : NN - 1)) * KK;
    const float* bp1 = bias + ((size_t)h * NN + (nrow1 < NN ? nrow1 : NN - 1)) * KK;
#pragma unroll
    for (int j = 0; j < NJT; j++) {
        int k0 = j * 8 + 2 * t4;
        s[j][0] = (k0     < KK) ? fmaf(s[j][0], 0.125f, bp0[k0])     : -1e30f;
        s[j][1] = (k0 + 1 < KK) ? fmaf(s[j][1], 0.125f, bp0[k0 + 1]) : -1e30f;
        s[j][2] = (k0     < KK) ? fmaf(s[j][2], 0.125f, bp1[k0])     : -1e30f;
        s[j][3] = (k0 + 1 < KK) ? fmaf(s[j][3], 0.125f, bp1[k0 + 1]) : -1e30f;
    }

    // ---- row softmax ----
    float m0 = -1e30f, m1 = -1e30f;
#pragma unroll
    for (int j = 0; j < NJT; j++) {
        m0 = fmaxf(m0, fmaxf(s[j][0], s[j][1]));
        m1 = fmaxf(m1, fmaxf(s[j][2], s[j][3]));
    }
    m0 = fmaxf(m0, __shfl_xor_sync(0xffffffffu, m0, 1));
    m0 = fmaxf(m0, __shfl_xor_sync(0xffffffffu, m0, 2));
    m1 = fmaxf(m1, __shfl_xor_sync(0xffffffffu, m1, 1));
    m1 = fmaxf(m1, __shfl_xor_sync(0xffffffffu, m1, 2));

    float l0 = 0.f, l1 = 0.f;
#pragma unroll
    for (int j = 0; j < NJT; j++) {
        s[j][0] = __expf(s[j][0] - m0); l0 += s[j][0];
        s[j][1] = __expf(s[j][1] - m0); l0 += s[j][1];
        s[j][2] = __expf(s[j][2] - m1); l1 += s[j][2];
        s[j][3] = __expf(s[j][3] - m1); l1 += s[j][3];
    }
    l0 += __shfl_xor_sync(0xffffffffu, l0, 1);
    l0 += __shfl_xor_sync(0xffffffffu, l0, 2);
    l1 += __shfl_xor_sync(0xffffffffu, l1, 1);
    l1 += __shfl_xor_sync(0xffffffffu, l1, 2);

    // ---- P @ V ----
    float ov[8][4];
#pragma unroll
    for (int t = 0; t < 8; t++)
        ov[t][0] = ov[t][1] = ov[t][2] = ov[t][3] = 0.f;

    const int src0 = (lane & ~3) | (t4 >> 1);
    const int src2 = src0 + 2;
    const bool odd = (t4 & 1);
#pragma unroll
    for (int j = 0; j < NJT; j++) {
        float v00 = __shfl_sync(0xffffffffu, s[j][0], src0);
        float v01 = __shfl_sync(0xffffffffu, s[j][1], src0);
        float v20 = __shfl_sync(0xffffffffu, s[j][2], src0);
        float v21 = __shfl_sync(0xffffffffu, s[j][3], src0);
        float w00 = __shfl_sync(0xffffffffu, s[j][0], src2);
        float w01 = __shfl_sync(0xffffffffu, s[j][1], src2);
        float w20 = __shfl_sync(0xffffffffu, s[j][2], src2);
        float w21 = __shfl_sync(0xffffffffu, s[j][3], src2);
        unsigned ap[4];
        ap[0] = f2tf(odd ? v01 : v00);
        ap[1] = f2tf(odd ? v21 : v20);
        ap[2] = f2tf(odd ? w01 : w00);
        ap[3] = f2tf(odd ? w21 : w20);
#pragma unroll
        for (int t = 0; t < 8; t++) {
            unsigned bf[2];
            const unsigned* vp = Vs + (j * 8 + t4) * VSTR + t * 8 + g;
            bf[0] = vp[0];
            bf[1] = vp[4 * VSTR];
            MMA_TF32(ov[t], ap, bf);
        }
    }

    // ---- epilogue: normalize, round to tf32, store ----
    const float inv0 = 1.f / l0, inv1 = 1.f / l1;
#pragma unroll
    for (int t = 0; t < 8; t++) {
        int col = h * 64 + t * 8 + 2 * t4;
        if (nrow0 < NN)
            *(float2*)(o + ((size_t)b * NN + nrow0) * DD + col) =
                make_float2(rtf(ov[t][0] * inv0), rtf(ov[t][1] * inv0));
        if (nrow1 < NN)
            *(float2*)(o + ((size_t)b * NN + nrow1) * DD + col) =
                make_float2(rtf(ov[t][2] * inv1), rtf(ov[t][3] * inv1));
    }
}

// ---------------- launch ----------------
extern "C" void kernel_launch(void* const* d_in, const int* in_sizes, int n_in,
                              void* d_out, int out_size)
{
    const float* x     = (const float*)d_in[0];
    const float* Wl    = (const float*)d_in[1];
    const float* Wq    = (const float*)d_in[2];
    const float* Wkv   = (const float*)d_in[3];
    const float* Wo    = (const float*)d_in[4];
    const float* bo    = (const float*)d_in[5];
    const float* w1    = (const float*)d_in[6];
    const float* b1    = (const float*)d_in[7];
    const float* w2    = (const float*)d_in[8];
    const float* b2    = (const float*)d_in[9];
    const float* feats = (const float*)d_in[10];
    const float* mask  = (const float*)d_in[11];
    float* out = (float*)d_out;

    float *ctx, *xr, *qb, *kvb, *biasb, *ob, *wqr, *wkvr, *wor;
    cudaGetSymbolAddress((void**)&ctx,   g_ctx);
    cudaGetSymbolAddress((void**)&xr,    g_xr);
    cudaGetSymbolAddress((void**)&qb,    g_q);
    cudaGetSymbolAddress((void**)&kvb,   g_kv);
    cudaGetSymbolAddress((void**)&biasb, g_bias);
    cudaGetSymbolAddress((void**)&ob,    g_o);
    cudaGetSymbolAddress((void**)&wqr,   g_wqr);
    cudaGetSymbolAddress((void**)&wkvr,  g_wkvr);
    cudaGetSymbolAddress((void**)&wor,   g_wor);

    const int ATTN_SMEM = (QT * QSTR + KP * KSTR + KP * VSTR) * 4; // 182656 B
    cudaFuncSetAttribute(attn_mma, cudaFuncAttributeMaxDynamicSharedMemorySize,
                         ATTN_SMEM);
    cudaFuncSetAttribute(gemm_tf32, cudaFuncAttributeMaxDynamicSharedMemorySize,
                         GEMM_SMEM);

    // 0. round weights to tf32 (tiny)
    const int W1N4 = DD * DD / 4, W2N4 = 2 * DD * DD / 4;
    round_kernel<<<(W1N4 + 255) / 256, 256>>>(Wq,  wqr,  W1N4);
    round_kernel<<<(W2N4 + 255) / 256, 256>>>(Wkv, wkvr, W2N4);
    round_kernel<<<(W1N4 + 255) / 256, 256>>>(Wo,  wor,  W1N4);
    // 1. pooled context (rounded) + rounded x copy
    pool_kernel<<<dim3(KK, BB), 256>>>(x, Wl, ctx, xr);
    // 2. Q = xr @ Wq^T    [32800,768]  grid: N/256=3, ceil(M/128)=257
    gemm_tf32<<<dim3(3, 257), 256, GEMM_SMEM>>>(xr, wqr, qb, BB * NN, DD, DD, nullptr);
    // 3. KV = ctx @ Wkv^T [8224,1536]  grid: 1536/256=6, ceil(8224/128)=65
    gemm_tf32<<<dim3(6, 65), 256, GEMM_SMEM>>>(ctx, wkvr, kvb, BB * KK, 2 * DD, DD, nullptr);
    // 4. CPB bias [12,1025,257]
    cpb_kernel<<<(NK + 127) / 128, 128>>>(feats, mask, w1, b1, w2, b2, biasb);
    // 5. mma attention (writes rounded o)
    attn_mma<<<dim3((NN + QT - 1) / QT, HH, BB), 256, ATTN_SMEM>>>(qb, kvb, biasb, ob);
    // 6. out = o @ Wo^T + bo
    gemm_tf32<<<dim3(3, 257), 256, GEMM_SMEM>>>(ob, wor, out, BB * NN, DD, DD, bo);
}